// round 14
// baseline (speedup 1.0000x reference)
#include <cuda_runtime.h>
#include <cuda_fp16.h>
#include <cstdint>

#define CDIM 256
#define KDIM 2048

// ---------------------------------------------------------------------------
// Scratch (allocation-free rule): mapping tables + pre-rounded B (fp16).
__device__ int g_src[131072];   // per merged position: source x-row if leaf, -1 if nonleaf
__device__ int g_dest[131072];  // per nonleaf rank: destination out-row
__device__ __half g_bhi[CDIM * KDIM];   // 1 MB

// ---------------------------------------------------------------------------
__device__ __forceinline__ uint32_t smem_to_u32(const void* p) {
    uint32_t a;
    asm("{ .reg .u64 t; cvta.to.shared.u64 t, %1; cvt.u32.u64 %0, t; }" : "=r"(a) : "l"(p));
    return a;
}

#define LDSM_X4(r0, r1, r2, r3, addr) \
    asm volatile("ldmatrix.sync.aligned.m8n8.x4.shared.b16 {%0,%1,%2,%3}, [%4];" \
                 : "=r"(r0), "=r"(r1), "=r"(r2), "=r"(r3) : "r"(addr))

#define MMA16816(d, a, b0_, b1_) \
    asm volatile("mma.sync.aligned.m16n8k16.row.col.f32.f16.f16.f32 " \
                 "{%0,%1,%2,%3}, {%4,%5,%6,%7}, {%8,%9}, {%0,%1,%2,%3};" \
                 : "+f"((d)[0]), "+f"((d)[1]), "+f"((d)[2]), "+f"((d)[3]) \
                 : "r"((a)[0]), "r"((a)[1]), "r"((a)[2]), "r"((a)[3]), \
                   "r"(b0_), "r"(b1_))

#define STS128(addr, r0, r1, r2, r3) \
    asm volatile("st.shared.v4.b32 [%0], {%1, %2, %3, %4};" \
                 :: "r"(addr), "r"(r0), "r"(r1), "r"(r2), "r"(r3) : "memory")

#define CPASYNC16(dst, src) \
    asm volatile("cp.async.ca.shared.global [%0], [%1], 16;" \
                 :: "r"(dst), "l"(src) : "memory")
#define CPASYNC_COMMIT() asm volatile("cp.async.commit_group;" ::: "memory")
#define CPASYNC_WAIT0()  asm volatile("cp.async.wait_group 0;" ::: "memory")

// Round fp32[8] to packed fp16x2 pairs
__device__ __forceinline__ void cvt8h(const float* f, uint32_t* hv) {
#pragma unroll
    for (int e = 0; e < 4; e++) {
        __half2 h = __floats2half2_rn(f[2 * e], f[2 * e + 1]);
        hv[e] = *(uint32_t*)&h;
    }
}

// ---------------- prep kernel: bsplit (blocks 1..128) + full scan (block 0) ----
// Block 0, 1024 threads: single-block leaf scan over children.
//   Thread q owns contiguous chunk [q*ck, min((q+1)*ck, T)). Pass 1 counts
//   leaves; block-wide exclusive scan gives each thread its starting
//   rank_leaf; pass 2 replays the chunk writing g_src/g_dest with the
//   validated scan3 recurrence.
// Blocks 1..128: B pre-round fp32 -> fp16 into g_bhi (4 floats per thread).
__global__ void __launch_bounds__(1024)
prep_kernel(const float* __restrict__ B, const int* __restrict__ ch,
            int T, int prefix) {
    int t = threadIdx.x;
    if (blockIdx.x > 0) {
        // ---- bsplit: 128 blocks x 1024 threads x 4 floats = 524288 ----
        int i = (((int)blockIdx.x - 1) * 1024 + t) * 4;
        float4 v = *(const float4*)(B + i);
        float f[4] = {v.x, v.y, v.z, v.w};
        __half hi[4];
#pragma unroll
        for (int e = 0; e < 4; e++) hi[e] = __float2half_rn(f[e]);
        *(uint2*)&g_bhi[i] = *(uint2*)hi;
        return;
    }

    // ---- block 0: single-block scan ----
    __shared__ int s[1024];
    int ck = (T + 1023) / 1024;           // chunk size per thread
    int lo = t * ck;
    int hi = min(lo + ck, T);

    // pass 1: count leaves in my chunk
    int c = 0;
    for (int i = lo; i < hi; i++)
        if (ch[i] < 0) c++;
    s[t] = c;
    __syncthreads();
    // inclusive Hillis-Steele scan over 1024 partials
    for (int off = 1; off < 1024; off <<= 1) {
        int u = (t >= off) ? s[t - off] : 0;
        __syncthreads();
        s[t] += u;
        __syncthreads();
    }
    int rl = s[t] - c;                    // exclusive: leaves strictly before lo

    // pass 2: write mapping (validated scan3 recurrence)
    for (int i = lo; i < hi; i++) {
        if (ch[i] < 0) {
            g_src[i] = prefix + rl;       // x_leaf row = prefix + rank_leaf
            rl++;
        } else {
            g_src[i] = -1;
            g_dest[i - rl] = prefix + i;  // rank_nonleaf = i - rank_leaf
        }
    }
}

// ---------------- fused GEMM + row-copy kernel ----------------
// Blocks [0, ngemm): single-product fp16 mma.sync GEMM, KC=32, depth-2
// pipeline (exact R10 structure, validated). Blocks [ngemm, ...): copy,
// one 128-byte batch per thread (8-deep MLP; fixes the R12 regression).
#define BM 128
#define BN 128
#define ROWB 80                 // padded row stride in bytes (32 fp16 = 64B + 16 pad)
#define TILE_B (128 * ROWB)     // 10240 bytes per operand tile
#define OFF_A 0
#define OFF_B (TILE_B)
#define STAGE_B (2 * TILE_B)    // 20480
#define GEMM_SMEM (2 * STAGE_B) // 40960

__global__ void __launch_bounds__(256, 2)
fused_kernel(const float* __restrict__ A, const float* __restrict__ x,
             float* __restrict__ out, int M, int K,
             int ngemm, int prefix, int R) {
    int t = threadIdx.x;

    // ---------------- copy branch (trailing blocks) ----------------
    if ((int)blockIdx.x >= ngemm) {
        // batch index: 8 batches of 128B per 1KB row
        int b = (blockIdx.x - ngemm) * 256 + t;
        int nbatch = R * 8;
        if (b >= nbatch) return;
        int r = b >> 3;
        int f0 = (b & 7) * 32;                // float offset within row
        int src;
        bool valid = true;
        if (r < prefix) {
            src = r;
        } else {
            src = g_src[r - prefix];
            if (src < 0) { valid = false; src = 0; }  // clamp; store suppressed
        }
        const float4* sp = (const float4*)(x + (size_t)src * CDIM + f0);
        float4 v[8];
#pragma unroll
        for (int j = 0; j < 8; j++) v[j] = sp[j];     // 8 independent LDGs
        if (valid) {
            float4* dp = (float4*)(out + (size_t)r * CDIM + f0);
#pragma unroll
            for (int j = 0; j < 8; j++) dp[j] = v[j];
        }
        return;
    }

    // ---------------- GEMM branch (leading blocks) ----------------
    extern __shared__ char smem[];
    uint32_t sb = smem_to_u32(smem);
    int lane = t & 31, wid = t >> 5;
    int warp_m = wid & 3, warp_n = wid >> 2;      // 4 x 2 warp grid
    int bm = ((int)blockIdx.x >> 1) * BM;         // N-fast pairing: adjacent
    int bn = ((int)blockIdx.x & 1) * BN;          // bids share the A tile

    // ldmatrix source offsets (stage-relative, bytes); k-step s adds s*32.
    uint32_t aoff0 = (uint32_t)(warp_m * 32 + (lane & 15)) * ROWB + ((lane >> 4) << 4);
    uint32_t aoff1 = aoff0 + 16 * ROWB;
    uint32_t boff[4];
#pragma unroll
    for (int np = 0; np < 4; np++)
        boff[np] = (uint32_t)(warp_n * 64 + np * 16 + ((lane >> 4) << 3) + (lane & 7)) * ROWB +
                   (((lane >> 3) & 1) << 4);

    // A loader: thread t handles row t>>1, 16-col half (t&1) of the 32-col chunk.
    int lrow = t >> 1;
    int lcolA = (t & 1) * 16;
    uint32_t soffa = (uint32_t)lrow * ROWB + lcolA * 2;   // 32 bytes per thread
    bool arow_ok = (bm + lrow) < M;
    const float* apix = A + (size_t)(bm + lrow) * K + lcolA;

    // B loader: thread t handles row t>>1, 32-byte half (t&1) of the 64-byte row.
    const __half* bhix = g_bhi + (size_t)(bn + lrow) * K + (t & 1) * 16;
    uint32_t soffb = (uint32_t)lrow * ROWB + (t & 1) * 32;

    float d[2][8][4];
#pragma unroll
    for (int mt = 0; mt < 2; mt++)
#pragma unroll
        for (int nt = 0; nt < 8; nt++)
#pragma unroll
            for (int e = 0; e < 4; e++) d[mt][nt][e] = 0.f;

    int nchunks = K >> 5;                     // 64
    float4 va[4];

    // Prologue: stage chunk 0 into buffer 0
    {
        if (arow_ok) {
            va[0] = *(const float4*)apix;      va[1] = *(const float4*)(apix + 4);
            va[2] = *(const float4*)(apix + 8); va[3] = *(const float4*)(apix + 12);
        } else {
            va[0] = va[1] = va[2] = va[3] = make_float4(0.f, 0.f, 0.f, 0.f);
        }
        float fa[16] = {va[0].x, va[0].y, va[0].z, va[0].w,
                        va[1].x, va[1].y, va[1].z, va[1].w,
                        va[2].x, va[2].y, va[2].z, va[2].w,
                        va[3].x, va[3].y, va[3].z, va[3].w};
        uint32_t hv[8];
        cvt8h(fa, hv);
        cvt8h(fa + 8, hv + 4);
        STS128(sb + OFF_A + soffa, hv[0], hv[1], hv[2], hv[3]);
        STS128(sb + OFF_A + soffa + 16, hv[4], hv[5], hv[6], hv[7]);
        CPASYNC16(sb + OFF_B + soffb, bhix);
        CPASYNC16(sb + OFF_B + soffb + 16, bhix + 8);
        CPASYNC_COMMIT();
        CPASYNC_WAIT0();
    }
    __syncthreads();

    for (int i = 0; i < nchunks; i++) {
        uint32_t st = sb + (uint32_t)(i & 1) * STAGE_B;
        uint32_t stn = sb + (uint32_t)((i + 1) & 1) * STAGE_B;
        bool more = (i + 1) < nchunks;

        // Issue next chunk's B cp.async + A global loads (overlap with MMAs)
        if (more) {
            int k0n = (i + 1) << 5;
            CPASYNC16(stn + OFF_B + soffb, bhix + k0n);
            CPASYNC16(stn + OFF_B + soffb + 16, bhix + k0n + 8);
            CPASYNC_COMMIT();
            if (arow_ok) {
                va[0] = *(const float4*)(apix + k0n);
                va[1] = *(const float4*)(apix + k0n + 4);
                va[2] = *(const float4*)(apix + k0n + 8);
                va[3] = *(const float4*)(apix + k0n + 12);
            }
        }

        // Compute chunk i: two k16 steps
#pragma unroll
        for (int s = 0; s < 2; s++) {
            uint32_t ks = (uint32_t)s * 32;
            uint32_t a0[2][4];
            LDSM_X4(a0[0][0], a0[0][1], a0[0][2], a0[0][3], st + OFF_A + aoff0 + ks);
            LDSM_X4(a0[1][0], a0[1][1], a0[1][2], a0[1][3], st + OFF_A + aoff1 + ks);
#pragma unroll
            for (int np = 0; np < 4; np++) {
                uint32_t bh[4];
                LDSM_X4(bh[0], bh[1], bh[2], bh[3], st + OFF_B + boff[np] + ks);
#pragma unroll
                for (int mt = 0; mt < 2; mt++) {
                    MMA16816(d[mt][np * 2], a0[mt], bh[0], bh[1]);
                    MMA16816(d[mt][np * 2 + 1], a0[mt], bh[2], bh[3]);
                }
            }
        }

        // Stage next A tile, drain B cp.async, publish buffer
        if (more) {
            float fa[16] = {va[0].x, va[0].y, va[0].z, va[0].w,
                            va[1].x, va[1].y, va[1].z, va[1].w,
                            va[2].x, va[2].y, va[2].z, va[2].w,
                            va[3].x, va[3].y, va[3].z, va[3].w};
            uint32_t hv[8];
            cvt8h(fa, hv);
            cvt8h(fa + 8, hv + 4);
            STS128(stn + OFF_A + soffa, hv[0], hv[1], hv[2], hv[3]);
            STS128(stn + OFF_A + soffa + 16, hv[4], hv[5], hv[6], hv[7]);
            CPASYNC_WAIT0();
            __syncthreads();
        }
    }

    // Epilogue: scatter rows through g_dest.
#pragma unroll
    for (int mt = 0; mt < 2; mt++) {
        int m = bm + warp_m * 32 + mt * 16 + (lane >> 2);
        int dr0 = (m < M) ? g_dest[m] : -1;
        int dr1 = (m + 8 < M) ? g_dest[m + 8] : -1;
        int colb = bn + warp_n * 64 + (lane & 3) * 2;
#pragma unroll
        for (int nt = 0; nt < 8; nt++) {
            int col = colb + nt * 8;
            if (dr0 >= 0)
                *(float2*)(out + (size_t)dr0 * CDIM + col) =
                    make_float2(d[mt][nt][0], d[mt][nt][1]);
            if (dr1 >= 0)
                *(float2*)(out + (size_t)dr1 * CDIM + col) =
                    make_float2(d[mt][nt][2], d[mt][nt][3]);
        }
    }
}

extern "C" void kernel_launch(void* const* d_in, const int* in_sizes, int n_in,
                              void* d_out, int out_size) {
    const float* x = (const float*)d_in[0];
    const float* w = (const float*)d_in[1];
    const int* ch = (const int*)d_in[2];
    float* out = (float*)d_out;

    const int C = CDIM;
    long n_rows = (long)in_sizes[0] / C;
    int T = in_sizes[2];                       // leaf_num + nonleaf count
    int out_rows = out_size / C;
    int prefix = out_rows - T;
    long rem = n_rows - prefix;                // = L + numd,  numd = 8*(T - L)
    int L = (int)((8L * T - rem) / 7);
    int Dn = T - L;                            // nonleaf count = GEMM M
    long numd = 8L * Dn;
    int K = 8 * C;                             // 2048

    const float* A = x + (size_t)(n_rows - numd) * C;

    // One prep launch: block 0 = full scan, blocks 1..128 = B pre-round.
    prep_kernel<<<1 + (CDIM * KDIM) / 4096, 1024>>>(w, ch, T, prefix);

    int ngemm = ((Dn + BM - 1) / BM) * 2;      // 782: GEMM blocks first
    int ncopy = (out_rows * 8 + 255) / 256;    // 938: one 128B batch per thread
    cudaFuncSetAttribute(fused_kernel, cudaFuncAttributeMaxDynamicSharedMemorySize,
                         GEMM_SMEM);
    fused_kernel<<<ngemm + ncopy, 256, GEMM_SMEM>>>(A, x, out, Dn, K,
                                                    ngemm, prefix, out_rows);
}

// round 15
// speedup vs baseline: 1.3043x; 1.3043x over previous
#include <cuda_runtime.h>
#include <cuda_fp16.h>
#include <cstdint>

#define CDIM 256
#define KDIM 2048

// ---------------------------------------------------------------------------
// Scratch (allocation-free rule): mapping tables + pre-rounded B (fp16).
__device__ int g_src[131072];   // per merged position: source x-row if leaf, -1 if nonleaf
__device__ int g_dest[131072];  // per nonleaf rank: destination out-row
__device__ int g_blkcnt[1024];
__device__ int g_blkoff[1024];
__device__ __half g_bhi[CDIM * KDIM];   // 1 MB

// ---------------------------------------------------------------------------
__device__ __forceinline__ uint32_t smem_to_u32(const void* p) {
    uint32_t a;
    asm("{ .reg .u64 t; cvta.to.shared.u64 t, %1; cvt.u32.u64 %0, t; }" : "=r"(a) : "l"(p));
    return a;
}

#define LDSM_X4(r0, r1, r2, r3, addr) \
    asm volatile("ldmatrix.sync.aligned.m8n8.x4.shared.b16 {%0,%1,%2,%3}, [%4];" \
                 : "=r"(r0), "=r"(r1), "=r"(r2), "=r"(r3) : "r"(addr))

#define MMA16816(d, a, b0_, b1_) \
    asm volatile("mma.sync.aligned.m16n8k16.row.col.f32.f16.f16.f32 " \
                 "{%0,%1,%2,%3}, {%4,%5,%6,%7}, {%8,%9}, {%0,%1,%2,%3};" \
                 : "+f"((d)[0]), "+f"((d)[1]), "+f"((d)[2]), "+f"((d)[3]) \
                 : "r"((a)[0]), "r"((a)[1]), "r"((a)[2]), "r"((a)[3]), \
                   "r"(b0_), "r"(b1_))

#define STS128(addr, r0, r1, r2, r3) \
    asm volatile("st.shared.v4.b32 [%0], {%1, %2, %3, %4};" \
                 :: "r"(addr), "r"(r0), "r"(r1), "r"(r2), "r"(r3) : "memory")

#define CPASYNC16(dst, src) \
    asm volatile("cp.async.ca.shared.global [%0], [%1], 16;" \
                 :: "r"(dst), "l"(src) : "memory")
#define CPASYNC_COMMIT() asm volatile("cp.async.commit_group;" ::: "memory")
#define CPASYNC_WAIT0()  asm volatile("cp.async.wait_group 0;" ::: "memory")

// Round fp32[8] to packed fp16x2 pairs
__device__ __forceinline__ void cvt8h(const float* f, uint32_t* hv) {
#pragma unroll
    for (int e = 0; e < 4; e++) {
        __half2 h = __floats2half2_rn(f[2 * e], f[2 * e + 1]);
        hv[e] = *(uint32_t*)&h;
    }
}

// ---------------- B pre-round: fp32 -> fp16 ----------------
__global__ void bsplit_kernel(const float* __restrict__ B) {
    int i = (blockIdx.x * 256 + threadIdx.x) * 4;
    float4 v = *(const float4*)(B + i);
    float f[4] = {v.x, v.y, v.z, v.w};
    __half hi[4];
#pragma unroll
    for (int e = 0; e < 4; e++) hi[e] = __float2half_rn(f[e]);
    *(uint2*)&g_bhi[i] = *(uint2*)hi;
}

// ---------------- scan stage 1: leaf count per 1024-elem chunk ----------------
__global__ void scan1_kernel(const int* __restrict__ ch, int T) {
    int b = blockIdx.x, t = threadIdx.x;
    __shared__ int s[256];
    int base = b * 1024 + t * 4;
    int c = 0;
#pragma unroll
    for (int j = 0; j < 4; j++) {
        int i = base + j;
        if (i < T && ch[i] < 0) c++;
    }
    s[t] = c;
    __syncthreads();
    for (int off = 128; off > 0; off >>= 1) {
        if (t < off) s[t] += s[t + off];
        __syncthreads();
    }
    if (t == 0) g_blkcnt[b] = s[0];
}

// ---------------- scan stage 2: exclusive scan of block counts ----------------
__global__ void scan2_kernel(int nb) {
    int t = threadIdx.x;
    __shared__ int s[1024];
    int v = (t < nb) ? g_blkcnt[t] : 0;
    s[t] = v;
    __syncthreads();
    for (int off = 1; off < 1024; off <<= 1) {
        int u = (t >= off) ? s[t - off] : 0;
        __syncthreads();
        s[t] += u;
        __syncthreads();
    }
    if (t < nb) g_blkoff[t] = s[t] - v;   // exclusive
}

// ---------------- scan stage 3: write src/dest mapping ----------------
__global__ void scan3_kernel(const int* __restrict__ ch, int T, int prefix) {
    int b = blockIdx.x, t = threadIdx.x;
    __shared__ int s[256];
    int base = b * 1024 + t * 4;
    int lm[4];
    int c = 0;
#pragma unroll
    for (int j = 0; j < 4; j++) {
        int i = base + j;
        lm[j] = (i < T && ch[i] < 0) ? 1 : 0;
        c += lm[j];
    }
    s[t] = c;
    __syncthreads();
    for (int off = 1; off < 256; off <<= 1) {
        int u = (t >= off) ? s[t - off] : 0;
        __syncthreads();
        s[t] += u;
        __syncthreads();
    }
    int rl = g_blkoff[b] + (s[t] - c);
#pragma unroll
    for (int j = 0; j < 4; j++) {
        int i = base + j;
        if (i < T) {
            if (lm[j]) {
                g_src[i] = prefix + rl;          // x_leaf row = prefix + rank_leaf
                rl++;
            } else {
                g_src[i] = -1;
                g_dest[i - rl] = prefix + i;     // rank_nonleaf = i - rank_leaf
            }
        }
    }
}

// ---------------- fused GEMM + row-copy kernel ----------------
// Blocks [0, ngemm): fp16 mma.sync GEMM, CTA tile 256x128, warp tile 64x64
// (8 warps as 4Mx2N), KC=32, depth-2 pipeline (validated skeleton).
// 64x64 warp tile cuts LDSM wavefronts per MMA from 0.375 to 0.25 — ncu
// showed L1 at 93.4% as the binding resource. Costs occupancy 1 (128
// accum regs/thread).
// Blocks [ngemm, ...): copy, one 128-byte batch per thread (8-deep MLP).
#define BM 256
#define BN 128
#define ROWB 80                 // padded row stride in bytes (32 fp16 = 64B + 16 pad)
#define A_TILE (BM * ROWB)      // 20480
#define B_TILE (BN * ROWB)      // 10240
#define OFF_A 0
#define OFF_B (A_TILE)
#define STAGE_B (A_TILE + B_TILE)   // 30720
#define GEMM_SMEM (2 * STAGE_B)     // 61440

__global__ void __launch_bounds__(256, 1)
fused_kernel(const float* __restrict__ A, const float* __restrict__ x,
             float* __restrict__ out, int M, int K,
             int ngemm, int prefix, int R) {
    int t = threadIdx.x;

    // ---------------- copy branch (trailing blocks) ----------------
    if ((int)blockIdx.x >= ngemm) {
        int b = (blockIdx.x - ngemm) * 256 + t;
        int nbatch = R * 8;
        if (b >= nbatch) return;
        int r = b >> 3;
        int f0 = (b & 7) * 32;                // float offset within row
        int src;
        bool valid = true;
        if (r < prefix) {
            src = r;
        } else {
            src = g_src[r - prefix];
            if (src < 0) { valid = false; src = 0; }  // clamp; store suppressed
        }
        const float4* sp = (const float4*)(x + (size_t)src * CDIM + f0);
        float4 v[8];
#pragma unroll
        for (int j = 0; j < 8; j++) v[j] = sp[j];     // 8 independent LDGs
        if (valid) {
            float4* dp = (float4*)(out + (size_t)r * CDIM + f0);
#pragma unroll
            for (int j = 0; j < 8; j++) dp[j] = v[j];
        }
        return;
    }

    // ---------------- GEMM branch (leading blocks) ----------------
    extern __shared__ char smem[];
    uint32_t sb = smem_to_u32(smem);
    int lane = t & 31, wid = t >> 5;
    int warp_m = wid & 3, warp_n = wid >> 2;      // 4 x 2 warp grid, 64x64 tiles
    int bm = ((int)blockIdx.x >> 1) * BM;         // N-fast pairing: adjacent
    int bn = ((int)blockIdx.x & 1) * BN;          // bids share the A tile

    // ldmatrix source offsets (stage-relative, bytes); k-step s adds s*32.
    uint32_t aoff = (uint32_t)(warp_m * 64 + (lane & 15)) * ROWB + ((lane >> 4) << 4);
    uint32_t boff[4];
#pragma unroll
    for (int np = 0; np < 4; np++)
        boff[np] = (uint32_t)(warp_n * 64 + np * 16 + ((lane >> 4) << 3) + (lane & 7)) * ROWB +
                   (((lane >> 3) & 1) << 4);

    // A loader: R13 mapping on two row-halves. Thread t handles rows
    // (t>>1) and (t>>1)+128, 16-col half (t&1) of the 32-col chunk.
    int lrow = t >> 1;
    int lcolA = (t & 1) * 16;
    uint32_t soffa0 = (uint32_t)lrow * ROWB + lcolA * 2;
    uint32_t soffa1 = soffa0 + 128 * ROWB;
    bool arow_ok0 = (bm + lrow) < M;
    bool arow_ok1 = (bm + lrow + 128) < M;
    const float* apix0 = A + (size_t)(bm + lrow) * K + lcolA;
    const float* apix1 = A + (size_t)(bm + lrow + 128) * K + lcolA;

    // B loader: thread t handles row t>>1, 32-byte half (t&1) of the 64-byte row.
    const __half* bhix = g_bhi + (size_t)(bn + lrow) * K + (t & 1) * 16;
    uint32_t soffb = (uint32_t)lrow * ROWB + (t & 1) * 32;

    float d[4][8][4];
#pragma unroll
    for (int mt = 0; mt < 4; mt++)
#pragma unroll
        for (int nt = 0; nt < 8; nt++)
#pragma unroll
            for (int e = 0; e < 4; e++) d[mt][nt][e] = 0.f;

    int nchunks = K >> 5;                     // 64
    float4 va0[4], va1[4];

    auto ldA = [&](int k0) {
        if (arow_ok0) {
            va0[0] = *(const float4*)(apix0 + k0);
            va0[1] = *(const float4*)(apix0 + k0 + 4);
            va0[2] = *(const float4*)(apix0 + k0 + 8);
            va0[3] = *(const float4*)(apix0 + k0 + 12);
        } else {
            va0[0] = va0[1] = va0[2] = va0[3] = make_float4(0.f, 0.f, 0.f, 0.f);
        }
        if (arow_ok1) {
            va1[0] = *(const float4*)(apix1 + k0);
            va1[1] = *(const float4*)(apix1 + k0 + 4);
            va1[2] = *(const float4*)(apix1 + k0 + 8);
            va1[3] = *(const float4*)(apix1 + k0 + 12);
        } else {
            va1[0] = va1[1] = va1[2] = va1[3] = make_float4(0.f, 0.f, 0.f, 0.f);
        }
    };
    auto stageA = [&](uint32_t dst) {
        float fa[16] = {va0[0].x, va0[0].y, va0[0].z, va0[0].w,
                        va0[1].x, va0[1].y, va0[1].z, va0[1].w,
                        va0[2].x, va0[2].y, va0[2].z, va0[2].w,
                        va0[3].x, va0[3].y, va0[3].z, va0[3].w};
        uint32_t hv[8];
        cvt8h(fa, hv);
        cvt8h(fa + 8, hv + 4);
        STS128(dst + OFF_A + soffa0, hv[0], hv[1], hv[2], hv[3]);
        STS128(dst + OFF_A + soffa0 + 16, hv[4], hv[5], hv[6], hv[7]);
        float fb[16] = {va1[0].x, va1[0].y, va1[0].z, va1[0].w,
                        va1[1].x, va1[1].y, va1[1].z, va1[1].w,
                        va1[2].x, va1[2].y, va1[2].z, va1[2].w,
                        va1[3].x, va1[3].y, va1[3].z, va1[3].w};
        cvt8h(fb, hv);
        cvt8h(fb + 8, hv + 4);
        STS128(dst + OFF_A + soffa1, hv[0], hv[1], hv[2], hv[3]);
        STS128(dst + OFF_A + soffa1 + 16, hv[4], hv[5], hv[6], hv[7]);
    };

    // Prologue: stage chunk 0 into buffer 0
    {
        ldA(0);
        stageA(sb);
        CPASYNC16(sb + OFF_B + soffb, bhix);
        CPASYNC16(sb + OFF_B + soffb + 16, bhix + 8);
        CPASYNC_COMMIT();
        CPASYNC_WAIT0();
    }
    __syncthreads();

    for (int i = 0; i < nchunks; i++) {
        uint32_t st = sb + (uint32_t)(i & 1) * STAGE_B;
        uint32_t stn = sb + (uint32_t)((i + 1) & 1) * STAGE_B;
        bool more = (i + 1) < nchunks;

        // Issue next chunk's B cp.async + A global loads (overlap with MMAs)
        if (more) {
            int k0n = (i + 1) << 5;
            CPASYNC16(stn + OFF_B + soffb, bhix + k0n);
            CPASYNC16(stn + OFF_B + soffb + 16, bhix + k0n + 8);
            CPASYNC_COMMIT();
            ldA(k0n);
        }

        // Compute chunk i: two k16 steps, 64x64 warp tile
#pragma unroll
        for (int s = 0; s < 2; s++) {
            uint32_t ks = (uint32_t)s * 32;
            uint32_t a0[4][4];
#pragma unroll
            for (int mt = 0; mt < 4; mt++)
                LDSM_X4(a0[mt][0], a0[mt][1], a0[mt][2], a0[mt][3],
                        st + OFF_A + aoff + (uint32_t)mt * 16 * ROWB + ks);
#pragma unroll
            for (int np = 0; np < 4; np++) {
                uint32_t bh[4];
                LDSM_X4(bh[0], bh[1], bh[2], bh[3], st + OFF_B + boff[np] + ks);
#pragma unroll
                for (int mt = 0; mt < 4; mt++) {
                    MMA16816(d[mt][np * 2], a0[mt], bh[0], bh[1]);
                    MMA16816(d[mt][np * 2 + 1], a0[mt], bh[2], bh[3]);
                }
            }
        }

        // Stage next A tile, drain B cp.async, publish buffer
        if (more) {
            stageA(stn);
            CPASYNC_WAIT0();
            __syncthreads();
        }
    }

    // Epilogue: scatter rows through g_dest.
#pragma unroll
    for (int mt = 0; mt < 4; mt++) {
        int m = bm + warp_m * 64 + mt * 16 + (lane >> 2);
        int dr0 = (m < M) ? g_dest[m] : -1;
        int dr1 = (m + 8 < M) ? g_dest[m + 8] : -1;
        int colb = bn + warp_n * 64 + (lane & 3) * 2;
#pragma unroll
        for (int nt = 0; nt < 8; nt++) {
            int col = colb + nt * 8;
            if (dr0 >= 0)
                *(float2*)(out + (size_t)dr0 * CDIM + col) =
                    make_float2(d[mt][nt][0], d[mt][nt][1]);
            if (dr1 >= 0)
                *(float2*)(out + (size_t)dr1 * CDIM + col) =
                    make_float2(d[mt][nt][2], d[mt][nt][3]);
        }
    }
}

extern "C" void kernel_launch(void* const* d_in, const int* in_sizes, int n_in,
                              void* d_out, int out_size) {
    const float* x = (const float*)d_in[0];
    const float* w = (const float*)d_in[1];
    const int* ch = (const int*)d_in[2];
    float* out = (float*)d_out;

    const int C = CDIM;
    long n_rows = (long)in_sizes[0] / C;
    int T = in_sizes[2];                       // leaf_num + nonleaf count
    int out_rows = out_size / C;
    int prefix = out_rows - T;
    long rem = n_rows - prefix;                // = L + numd,  numd = 8*(T - L)
    int L = (int)((8L * T - rem) / 7);
    int Dn = T - L;                            // nonleaf count = GEMM M
    long numd = 8L * Dn;
    int K = 8 * C;                             // 2048

    const float* A = x + (size_t)(n_rows - numd) * C;

    bsplit_kernel<<<(CDIM * KDIM) / 1024, 256>>>(w);

    int nb = (T + 1023) / 1024;
    scan1_kernel<<<nb, 256>>>(ch, T);
    scan2_kernel<<<1, 1024>>>(nb);
    scan3_kernel<<<nb, 256>>>(ch, T, prefix);

    int ngemm = ((Dn + BM - 1) / BM) * 2;      // 392: GEMM blocks first
    int ncopy = (out_rows * 8 + 255) / 256;    // 938: one 128B batch per thread
    cudaFuncSetAttribute(fused_kernel, cudaFuncAttributeMaxDynamicSharedMemorySize,
                         GEMM_SMEM);
    fused_kernel<<<ngemm + ncopy, 256, GEMM_SMEM>>>(A, x, out, Dn, K,
                                                    ngemm, prefix, out_rows);
}

// round 16
// speedup vs baseline: 1.3823x; 1.0598x over previous
#include <cuda_runtime.h>
#include <cuda_fp16.h>
#include <cstdint>

#define CDIM 256
#define KDIM 2048

// ---------------------------------------------------------------------------
// Scratch (allocation-free rule): mapping tables + pre-rounded B (fp16).
__device__ int g_src[131072];   // per merged position: source x-row if leaf, -1 if nonleaf
__device__ int g_dest[131072];  // per nonleaf rank: destination out-row
__device__ int g_blkcnt[1024];
__device__ int g_blkoff[1024];
__device__ __half g_bhi[CDIM * KDIM];   // 1 MB

// ---------------------------------------------------------------------------
__device__ __forceinline__ uint32_t smem_to_u32(const void* p) {
    uint32_t a;
    asm("{ .reg .u64 t; cvta.to.shared.u64 t, %1; cvt.u32.u64 %0, t; }" : "=r"(a) : "l"(p));
    return a;
}

#define LDSM_X4(r0, r1, r2, r3, addr) \
    asm volatile("ldmatrix.sync.aligned.m8n8.x4.shared.b16 {%0,%1,%2,%3}, [%4];" \
                 : "=r"(r0), "=r"(r1), "=r"(r2), "=r"(r3) : "r"(addr))

#define MMA16816(d, a, b0_, b1_) \
    asm volatile("mma.sync.aligned.m16n8k16.row.col.f32.f16.f16.f32 " \
                 "{%0,%1,%2,%3}, {%4,%5,%6,%7}, {%8,%9}, {%0,%1,%2,%3};" \
                 : "+f"((d)[0]), "+f"((d)[1]), "+f"((d)[2]), "+f"((d)[3]) \
                 : "r"((a)[0]), "r"((a)[1]), "r"((a)[2]), "r"((a)[3]), \
                   "r"(b0_), "r"(b1_))

#define STS128(addr, r0, r1, r2, r3) \
    asm volatile("st.shared.v4.b32 [%0], {%1, %2, %3, %4};" \
                 :: "r"(addr), "r"(r0), "r"(r1), "r"(r2), "r"(r3) : "memory")

#define CPASYNC16(dst, src) \
    asm volatile("cp.async.ca.shared.global [%0], [%1], 16;" \
                 :: "r"(dst), "l"(src) : "memory")
#define CPASYNC_COMMIT() asm volatile("cp.async.commit_group;" ::: "memory")
#define CPASYNC_WAIT0()  asm volatile("cp.async.wait_group 0;" ::: "memory")

// Round fp32[8] to packed fp16x2 pairs
__device__ __forceinline__ void cvt8h(const float* f, uint32_t* hv) {
#pragma unroll
    for (int e = 0; e < 4; e++) {
        __half2 h = __floats2half2_rn(f[2 * e], f[2 * e + 1]);
        hv[e] = *(uint32_t*)&h;
    }
}

// ---------------- scan1 + bsplit, one launch ----------------
// Blocks [0, nb): leaf count per 1024-elem chunk (validated scan1 body).
// Blocks [nb, nb+512): B pre-round fp32 -> fp16 (validated bsplit body).
// The two are independent (scan reads ch, bsplit reads B) so they run
// concurrently instead of as two serial launches.
__global__ void scan1_bsplit_kernel(const float* __restrict__ B,
                                    const int* __restrict__ ch, int T, int nb) {
    int t = threadIdx.x;
    if ((int)blockIdx.x >= nb) {
        // ---- bsplit branch ----
        int i = (((int)blockIdx.x - nb) * 256 + t) * 4;
        float4 v = *(const float4*)(B + i);
        float f[4] = {v.x, v.y, v.z, v.w};
        __half hi[4];
#pragma unroll
        for (int e = 0; e < 4; e++) hi[e] = __float2half_rn(f[e]);
        *(uint2*)&g_bhi[i] = *(uint2*)hi;
        return;
    }
    // ---- scan1 branch ----
    int b = blockIdx.x;
    __shared__ int s[256];
    int base = b * 1024 + t * 4;
    int c = 0;
#pragma unroll
    for (int j = 0; j < 4; j++) {
        int i = base + j;
        if (i < T && ch[i] < 0) c++;
    }
    s[t] = c;
    __syncthreads();
    for (int off = 128; off > 0; off >>= 1) {
        if (t < off) s[t] += s[t + off];
        __syncthreads();
    }
    if (t == 0) g_blkcnt[b] = s[0];
}

// ---------------- scan stage 2: exclusive scan of block counts ----------------
__global__ void scan2_kernel(int nb) {
    int t = threadIdx.x;
    __shared__ int s[1024];
    int v = (t < nb) ? g_blkcnt[t] : 0;
    s[t] = v;
    __syncthreads();
    for (int off = 1; off < 1024; off <<= 1) {
        int u = (t >= off) ? s[t - off] : 0;
        __syncthreads();
        s[t] += u;
        __syncthreads();
    }
    if (t < nb) g_blkoff[t] = s[t] - v;   // exclusive
}

// ---------------- scan stage 3: write src/dest mapping ----------------
__global__ void scan3_kernel(const int* __restrict__ ch, int T, int prefix) {
    int b = blockIdx.x, t = threadIdx.x;
    __shared__ int s[256];
    int base = b * 1024 + t * 4;
    int lm[4];
    int c = 0;
#pragma unroll
    for (int j = 0; j < 4; j++) {
        int i = base + j;
        lm[j] = (i < T && ch[i] < 0) ? 1 : 0;
        c += lm[j];
    }
    s[t] = c;
    __syncthreads();
    for (int off = 1; off < 256; off <<= 1) {
        int u = (t >= off) ? s[t - off] : 0;
        __syncthreads();
        s[t] += u;
        __syncthreads();
    }
    int rl = g_blkoff[b] + (s[t] - c);
#pragma unroll
    for (int j = 0; j < 4; j++) {
        int i = base + j;
        if (i < T) {
            if (lm[j]) {
                g_src[i] = prefix + rl;          // x_leaf row = prefix + rank_leaf
                rl++;
            } else {
                g_src[i] = -1;
                g_dest[i - rl] = prefix + i;     // rank_nonleaf = i - rank_leaf
            }
        }
    }
}

// ---------------- fused GEMM + row-copy kernel (R13, validated 319.5us) ----
// Blocks [0, ngemm): single-product fp16 mma.sync GEMM, KC=32, depth-2
// pipeline. Blocks [ngemm, ...): copy, one 128-byte batch per thread
// (8-deep MLP so the copy sustains DRAM BW at the GEMM's occupancy cap).
#define BM 128
#define BN 128
#define ROWB 80                 // padded row stride in bytes (32 fp16 = 64B + 16 pad)
#define TILE_B (128 * ROWB)     // 10240 bytes per operand tile
#define OFF_A 0
#define OFF_B (TILE_B)
#define STAGE_B (2 * TILE_B)    // 20480
#define GEMM_SMEM (2 * STAGE_B) // 40960

__global__ void __launch_bounds__(256, 2)
fused_kernel(const float* __restrict__ A, const float* __restrict__ x,
             float* __restrict__ out, int M, int K,
             int ngemm, int prefix, int R) {
    int t = threadIdx.x;

    // ---------------- copy branch (trailing blocks) ----------------
    if ((int)blockIdx.x >= ngemm) {
        // batch index: 8 batches of 128B per 1KB row
        int b = (blockIdx.x - ngemm) * 256 + t;
        int nbatch = R * 8;
        if (b >= nbatch) return;
        int r = b >> 3;
        int f0 = (b & 7) * 32;                // float offset within row
        int src;
        bool valid = true;
        if (r < prefix) {
            src = r;
        } else {
            src = g_src[r - prefix];
            if (src < 0) { valid = false; src = 0; }  // clamp; store suppressed
        }
        const float4* sp = (const float4*)(x + (size_t)src * CDIM + f0);
        float4 v[8];
#pragma unroll
        for (int j = 0; j < 8; j++) v[j] = sp[j];     // 8 independent LDGs
        if (valid) {
            float4* dp = (float4*)(out + (size_t)r * CDIM + f0);
#pragma unroll
            for (int j = 0; j < 8; j++) dp[j] = v[j];
        }
        return;
    }

    // ---------------- GEMM branch (leading blocks) ----------------
    extern __shared__ char smem[];
    uint32_t sb = smem_to_u32(smem);
    int lane = t & 31, wid = t >> 5;
    int warp_m = wid & 3, warp_n = wid >> 2;      // 4 x 2 warp grid
    int bm = ((int)blockIdx.x >> 1) * BM;         // N-fast pairing: adjacent
    int bn = ((int)blockIdx.x & 1) * BN;          // bids share the A tile

    // ldmatrix source offsets (stage-relative, bytes); k-step s adds s*32.
    uint32_t aoff0 = (uint32_t)(warp_m * 32 + (lane & 15)) * ROWB + ((lane >> 4) << 4);
    uint32_t aoff1 = aoff0 + 16 * ROWB;
    uint32_t boff[4];
#pragma unroll
    for (int np = 0; np < 4; np++)
        boff[np] = (uint32_t)(warp_n * 64 + np * 16 + ((lane >> 4) << 3) + (lane & 7)) * ROWB +
                   (((lane >> 3) & 1) << 4);

    // A loader: thread t handles row t>>1, 16-col half (t&1) of the 32-col chunk.
    int lrow = t >> 1;
    int lcolA = (t & 1) * 16;
    uint32_t soffa = (uint32_t)lrow * ROWB + lcolA * 2;   // 32 bytes per thread
    bool arow_ok = (bm + lrow) < M;
    const float* apix = A + (size_t)(bm + lrow) * K + lcolA;

    // B loader: thread t handles row t>>1, 32-byte half (t&1) of the 64-byte row.
    const __half* bhix = g_bhi + (size_t)(bn + lrow) * K + (t & 1) * 16;
    uint32_t soffb = (uint32_t)lrow * ROWB + (t & 1) * 32;

    float d[2][8][4];
#pragma unroll
    for (int mt = 0; mt < 2; mt++)
#pragma unroll
        for (int nt = 0; nt < 8; nt++)
#pragma unroll
            for (int e = 0; e < 4; e++) d[mt][nt][e] = 0.f;

    int nchunks = K >> 5;                     // 64
    float4 va[4];

    // Prologue: stage chunk 0 into buffer 0
    {
        if (arow_ok) {
            va[0] = *(const float4*)apix;      va[1] = *(const float4*)(apix + 4);
            va[2] = *(const float4*)(apix + 8); va[3] = *(const float4*)(apix + 12);
        } else {
            va[0] = va[1] = va[2] = va[3] = make_float4(0.f, 0.f, 0.f, 0.f);
        }
        float fa[16] = {va[0].x, va[0].y, va[0].z, va[0].w,
                        va[1].x, va[1].y, va[1].z, va[1].w,
                        va[2].x, va[2].y, va[2].z, va[2].w,
                        va[3].x, va[3].y, va[3].z, va[3].w};
        uint32_t hv[8];
        cvt8h(fa, hv);
        cvt8h(fa + 8, hv + 4);
        STS128(sb + OFF_A + soffa, hv[0], hv[1], hv[2], hv[3]);
        STS128(sb + OFF_A + soffa + 16, hv[4], hv[5], hv[6], hv[7]);
        CPASYNC16(sb + OFF_B + soffb, bhix);
        CPASYNC16(sb + OFF_B + soffb + 16, bhix + 8);
        CPASYNC_COMMIT();
        CPASYNC_WAIT0();
    }
    __syncthreads();

    for (int i = 0; i < nchunks; i++) {
        uint32_t st = sb + (uint32_t)(i & 1) * STAGE_B;
        uint32_t stn = sb + (uint32_t)((i + 1) & 1) * STAGE_B;
        bool more = (i + 1) < nchunks;

        // Issue next chunk's B cp.async + A global loads (overlap with MMAs)
        if (more) {
            int k0n = (i + 1) << 5;
            CPASYNC16(stn + OFF_B + soffb, bhix + k0n);
            CPASYNC16(stn + OFF_B + soffb + 16, bhix + k0n + 8);
            CPASYNC_COMMIT();
            if (arow_ok) {
                va[0] = *(const float4*)(apix + k0n);
                va[1] = *(const float4*)(apix + k0n + 4);
                va[2] = *(const float4*)(apix + k0n + 8);
                va[3] = *(const float4*)(apix + k0n + 12);
            }
        }

        // Compute chunk i: two k16 steps
#pragma unroll
        for (int s = 0; s < 2; s++) {
            uint32_t ks = (uint32_t)s * 32;
            uint32_t a0[2][4];
            LDSM_X4(a0[0][0], a0[0][1], a0[0][2], a0[0][3], st + OFF_A + aoff0 + ks);
            LDSM_X4(a0[1][0], a0[1][1], a0[1][2], a0[1][3], st + OFF_A + aoff1 + ks);
#pragma unroll
            for (int np = 0; np < 4; np++) {
                uint32_t bh[4];
                LDSM_X4(bh[0], bh[1], bh[2], bh[3], st + OFF_B + boff[np] + ks);
#pragma unroll
                for (int mt = 0; mt < 2; mt++) {
                    MMA16816(d[mt][np * 2], a0[mt], bh[0], bh[1]);
                    MMA16816(d[mt][np * 2 + 1], a0[mt], bh[2], bh[3]);
                }
            }
        }

        // Stage next A tile, drain B cp.async, publish buffer
        if (more) {
            float fa[16] = {va[0].x, va[0].y, va[0].z, va[0].w,
                            va[1].x, va[1].y, va[1].z, va[1].w,
                            va[2].x, va[2].y, va[2].z, va[2].w,
                            va[3].x, va[3].y, va[3].z, va[3].w};
            uint32_t hv[8];
            cvt8h(fa, hv);
            cvt8h(fa + 8, hv + 4);
            STS128(stn + OFF_A + soffa, hv[0], hv[1], hv[2], hv[3]);
            STS128(stn + OFF_A + soffa + 16, hv[4], hv[5], hv[6], hv[7]);
            CPASYNC_WAIT0();
            __syncthreads();
        }
    }

    // Epilogue: scatter rows through g_dest.
#pragma unroll
    for (int mt = 0; mt < 2; mt++) {
        int m = bm + warp_m * 32 + mt * 16 + (lane >> 2);
        int dr0 = (m < M) ? g_dest[m] : -1;
        int dr1 = (m + 8 < M) ? g_dest[m + 8] : -1;
        int colb = bn + warp_n * 64 + (lane & 3) * 2;
#pragma unroll
        for (int nt = 0; nt < 8; nt++) {
            int col = colb + nt * 8;
            if (dr0 >= 0)
                *(float2*)(out + (size_t)dr0 * CDIM + col) =
                    make_float2(d[mt][nt][0], d[mt][nt][1]);
            if (dr1 >= 0)
                *(float2*)(out + (size_t)dr1 * CDIM + col) =
                    make_float2(d[mt][nt][2], d[mt][nt][3]);
        }
    }
}

extern "C" void kernel_launch(void* const* d_in, const int* in_sizes, int n_in,
                              void* d_out, int out_size) {
    const float* x = (const float*)d_in[0];
    const float* w = (const float*)d_in[1];
    const int* ch = (const int*)d_in[2];
    float* out = (float*)d_out;

    const int C = CDIM;
    long n_rows = (long)in_sizes[0] / C;
    int T = in_sizes[2];                       // leaf_num + nonleaf count
    int out_rows = out_size / C;
    int prefix = out_rows - T;
    long rem = n_rows - prefix;                // = L + numd,  numd = 8*(T - L)
    int L = (int)((8L * T - rem) / 7);
    int Dn = T - L;                            // nonleaf count = GEMM M
    long numd = 8L * Dn;
    int K = 8 * C;                             // 2048

    const float* A = x + (size_t)(n_rows - numd) * C;

    int nb = (T + 1023) / 1024;
    int nbsplit = (CDIM * KDIM) / 1024;        // 512 blocks, 256 thr, 4 floats each
    scan1_bsplit_kernel<<<nb + nbsplit, 256>>>(w, ch, T, nb);
    scan2_kernel<<<1, 1024>>>(nb);
    scan3_kernel<<<nb, 256>>>(ch, T, prefix);

    int ngemm = ((Dn + BM - 1) / BM) * 2;      // 782: GEMM blocks first
    int ncopy = (out_rows * 8 + 255) / 256;    // 938: one 128B batch per thread
    cudaFuncSetAttribute(fused_kernel, cudaFuncAttributeMaxDynamicSharedMemorySize,
                         GEMM_SMEM);
    fused_kernel<<<ngemm + ncopy, 256, GEMM_SMEM>>>(A, x, out, Dn, K,
                                                    ngemm, prefix, out_rows);
}

// round 17
// speedup vs baseline: 1.3904x; 1.0059x over previous
#include <cuda_runtime.h>
#include <cuda_fp16.h>
#include <cstdint>

#define CDIM 256
#define KDIM 2048

// ---------------------------------------------------------------------------
// Scratch (allocation-free rule): mapping tables + pre-rounded B (fp16).
__device__ int g_src[131072];   // per merged position: source x-row if leaf, -1 if nonleaf
__device__ int g_dest[131072];  // per nonleaf rank: destination out-row
__device__ int g_blkcnt[1024];
__device__ volatile int g_done; // scan-complete flag (reset each call by launch 1)

__device__ __half g_bhi[CDIM * KDIM];   // 1 MB

// ---------------------------------------------------------------------------
__device__ __forceinline__ uint32_t smem_to_u32(const void* p) {
    uint32_t a;
    asm("{ .reg .u64 t; cvta.to.shared.u64 t, %1; cvt.u32.u64 %0, t; }" : "=r"(a) : "l"(p));
    return a;
}

#define LDSM_X4(r0, r1, r2, r3, addr) \
    asm volatile("ldmatrix.sync.aligned.m8n8.x4.shared.b16 {%0,%1,%2,%3}, [%4];" \
                 : "=r"(r0), "=r"(r1), "=r"(r2), "=r"(r3) : "r"(addr))

#define MMA16816(d, a, b0_, b1_) \
    asm volatile("mma.sync.aligned.m16n8k16.row.col.f32.f16.f16.f32 " \
                 "{%0,%1,%2,%3}, {%4,%5,%6,%7}, {%8,%9}, {%0,%1,%2,%3};" \
                 : "+f"((d)[0]), "+f"((d)[1]), "+f"((d)[2]), "+f"((d)[3]) \
                 : "r"((a)[0]), "r"((a)[1]), "r"((a)[2]), "r"((a)[3]), \
                   "r"(b0_), "r"(b1_))

#define STS128(addr, r0, r1, r2, r3) \
    asm volatile("st.shared.v4.b32 [%0], {%1, %2, %3, %4};" \
                 :: "r"(addr), "r"(r0), "r"(r1), "r"(r2), "r"(r3) : "memory")

#define CPASYNC16(dst, src) \
    asm volatile("cp.async.ca.shared.global [%0], [%1], 16;" \
                 :: "r"(dst), "l"(src) : "memory")
#define CPASYNC_COMMIT() asm volatile("cp.async.commit_group;" ::: "memory")
#define CPASYNC_WAIT0()  asm volatile("cp.async.wait_group 0;" ::: "memory")

// Round fp32[8] to packed fp16x2 pairs
__device__ __forceinline__ void cvt8h(const float* f, uint32_t* hv) {
#pragma unroll
    for (int e = 0; e < 4; e++) {
        __half2 h = __floats2half2_rn(f[2 * e], f[2 * e + 1]);
        hv[e] = *(uint32_t*)&h;
    }
}

// Wait until all scan blocks have published g_src/g_dest. One thread polls,
// then a block barrier releases everyone. Flag is reset by launch 1 each call.
__device__ __forceinline__ void wait_scan_done(int t, int nb) {
    if (t == 0) {
        while (g_done < nb) { }
    }
    __syncthreads();
}

// ---------------- launch 1: scan1 + bsplit (+ flag reset) ----------------
// Blocks [0, nb): leaf count per 1024-elem chunk (validated scan1 body).
// Blocks [nb, nb+512): B pre-round fp32 -> fp16 (validated bsplit body).
__global__ void scan1_bsplit_kernel(const float* __restrict__ B,
                                    const int* __restrict__ ch, int T, int nb) {
    int t = threadIdx.x;
    if (blockIdx.x == 0 && t == 0) g_done = 0;   // reset for this call/replay
    if ((int)blockIdx.x >= nb) {
        // ---- bsplit branch ----
        int i = (((int)blockIdx.x - nb) * 256 + t) * 4;
        float4 v = *(const float4*)(B + i);
        float f[4] = {v.x, v.y, v.z, v.w};
        __half hi[4];
#pragma unroll
        for (int e = 0; e < 4; e++) hi[e] = __float2half_rn(f[e]);
        *(uint2*)&g_bhi[i] = *(uint2*)hi;
        return;
    }
    // ---- scan1 branch ----
    int b = blockIdx.x;
    __shared__ int s[256];
    int base = b * 1024 + t * 4;
    int c = 0;
#pragma unroll
    for (int j = 0; j < 4; j++) {
        int i = base + j;
        if (i < T && ch[i] < 0) c++;
    }
    s[t] = c;
    __syncthreads();
    for (int off = 128; off > 0; off >>= 1) {
        if (t < off) s[t] += s[t + off];
        __syncthreads();
    }
    if (t == 0) g_blkcnt[b] = s[0];
}

// ---------------- fused scan3' + GEMM + row-copy kernel ----------------
// Blocks [0, nscan): scan stage 2+3 fused — each block recomputes the
//   exclusive prefix over g_blkcnt locally (nb<=256 values), then runs the
//   validated scan3 body; publishes via fence + g_done counter.
// Blocks [nscan, nscan+ngemm): fp16 mma.sync GEMM, KC=32, depth-2 (R13,
//   validated). Epilogue spins on g_done before reading g_dest.
// Remaining blocks: copy, one 128-byte batch/thread; spins on g_done first.
#define BM 128
#define BN 128
#define ROWB 80                 // padded row stride in bytes (32 fp16 = 64B + 16 pad)
#define TILE_B (128 * ROWB)     // 10240 bytes per operand tile
#define OFF_A 0
#define OFF_B (TILE_B)
#define STAGE_B (2 * TILE_B)    // 20480
#define GEMM_SMEM (2 * STAGE_B) // 40960

__global__ void __launch_bounds__(256, 2)
fused_kernel(const float* __restrict__ A, const float* __restrict__ x,
             const int* __restrict__ ch, float* __restrict__ out,
             int M, int K, int nscan, int ngemm, int prefix, int R, int T) {
    int t = threadIdx.x;

    // ---------------- scan branch (first blocks) ----------------
    if ((int)blockIdx.x < nscan) {
        int b = blockIdx.x;
        __shared__ int s[256];
        // stage 2 (per-block recompute): exclusive prefix of g_blkcnt[0..nscan)
        int v = (t < nscan) ? g_blkcnt[t] : 0;
        s[t] = v;
        __syncthreads();
        for (int off = 1; off < 256; off <<= 1) {
            int u = (t >= off) ? s[t - off] : 0;
            __syncthreads();
            s[t] += u;
            __syncthreads();
        }
        int blkoff = s[b] - g_blkcnt[b];   // exclusive offset for my block
        __syncthreads();
        // stage 3 (validated body)
        int base = b * 1024 + t * 4;
        int lm[4];
        int c = 0;
#pragma unroll
        for (int j = 0; j < 4; j++) {
            int i = base + j;
            lm[j] = (i < T && ch[i] < 0) ? 1 : 0;
            c += lm[j];
        }
        s[t] = c;
        __syncthreads();
        for (int off = 1; off < 256; off <<= 1) {
            int u = (t >= off) ? s[t - off] : 0;
            __syncthreads();
            s[t] += u;
            __syncthreads();
        }
        int rl = blkoff + (s[t] - c);
#pragma unroll
        for (int j = 0; j < 4; j++) {
            int i = base + j;
            if (i < T) {
                if (lm[j]) {
                    g_src[i] = prefix + rl;          // x_leaf row = prefix + rank_leaf
                    rl++;
                } else {
                    g_src[i] = -1;
                    g_dest[i - rl] = prefix + i;     // rank_nonleaf = i - rank_leaf
                }
            }
        }
        // publish
        __threadfence();
        __syncthreads();
        if (t == 0) atomicAdd((int*)&g_done, 1);
        return;
    }

    // ---------------- copy branch (trailing blocks) ----------------
    if ((int)blockIdx.x >= nscan + ngemm) {
        wait_scan_done(t, nscan);
        int b = (blockIdx.x - nscan - ngemm) * 256 + t;
        int nbatch = R * 8;
        if (b >= nbatch) return;
        int r = b >> 3;
        int f0 = (b & 7) * 32;                // float offset within row
        int src;
        bool valid = true;
        if (r < prefix) {
            src = r;
        } else {
            src = g_src[r - prefix];
            if (src < 0) { valid = false; src = 0; }  // clamp; store suppressed
        }
        const float4* sp = (const float4*)(x + (size_t)src * CDIM + f0);
        float4 v[8];
#pragma unroll
        for (int j = 0; j < 8; j++) v[j] = sp[j];     // 8 independent LDGs
        if (valid) {
            float4* dp = (float4*)(out + (size_t)r * CDIM + f0);
#pragma unroll
            for (int j = 0; j < 8; j++) dp[j] = v[j];
        }
        return;
    }

    // ---------------- GEMM branch (middle blocks) ----------------
    extern __shared__ char smem[];
    uint32_t sb = smem_to_u32(smem);
    int lane = t & 31, wid = t >> 5;
    int warp_m = wid & 3, warp_n = wid >> 2;      // 4 x 2 warp grid
    int gbid = (int)blockIdx.x - nscan;
    int bm = (gbid >> 1) * BM;                    // N-fast pairing: adjacent
    int bn = (gbid & 1) * BN;                     // bids share the A tile

    // ldmatrix source offsets (stage-relative, bytes); k-step s adds s*32.
    uint32_t aoff0 = (uint32_t)(warp_m * 32 + (lane & 15)) * ROWB + ((lane >> 4) << 4);
    uint32_t aoff1 = aoff0 + 16 * ROWB;
    uint32_t boff[4];
#pragma unroll
    for (int np = 0; np < 4; np++)
        boff[np] = (uint32_t)(warp_n * 64 + np * 16 + ((lane >> 4) << 3) + (lane & 7)) * ROWB +
                   (((lane >> 3) & 1) << 4);

    // A loader: thread t handles row t>>1, 16-col half (t&1) of the 32-col chunk.
    int lrow = t >> 1;
    int lcolA = (t & 1) * 16;
    uint32_t soffa = (uint32_t)lrow * ROWB + lcolA * 2;   // 32 bytes per thread
    bool arow_ok = (bm + lrow) < M;
    const float* apix = A + (size_t)(bm + lrow) * K + lcolA;

    // B loader: thread t handles row t>>1, 32-byte half (t&1) of the 64-byte row.
    const __half* bhix = g_bhi + (size_t)(bn + lrow) * K + (t & 1) * 16;
    uint32_t soffb = (uint32_t)lrow * ROWB + (t & 1) * 32;

    float d[2][8][4];
#pragma unroll
    for (int mt = 0; mt < 2; mt++)
#pragma unroll
        for (int nt = 0; nt < 8; nt++)
#pragma unroll
            for (int e = 0; e < 4; e++) d[mt][nt][e] = 0.f;

    int nchunks = K >> 5;                     // 64
    float4 va[4];

    // Prologue: stage chunk 0 into buffer 0
    {
        if (arow_ok) {
            va[0] = *(const float4*)apix;      va[1] = *(const float4*)(apix + 4);
            va[2] = *(const float4*)(apix + 8); va[3] = *(const float4*)(apix + 12);
        } else {
            va[0] = va[1] = va[2] = va[3] = make_float4(0.f, 0.f, 0.f, 0.f);
        }
        float fa[16] = {va[0].x, va[0].y, va[0].z, va[0].w,
                        va[1].x, va[1].y, va[1].z, va[1].w,
                        va[2].x, va[2].y, va[2].z, va[2].w,
                        va[3].x, va[3].y, va[3].z, va[3].w};
        uint32_t hv[8];
        cvt8h(fa, hv);
        cvt8h(fa + 8, hv + 4);
        STS128(sb + OFF_A + soffa, hv[0], hv[1], hv[2], hv[3]);
        STS128(sb + OFF_A + soffa + 16, hv[4], hv[5], hv[6], hv[7]);
        CPASYNC16(sb + OFF_B + soffb, bhix);
        CPASYNC16(sb + OFF_B + soffb + 16, bhix + 8);
        CPASYNC_COMMIT();
        CPASYNC_WAIT0();
    }
    __syncthreads();

    for (int i = 0; i < nchunks; i++) {
        uint32_t st = sb + (uint32_t)(i & 1) * STAGE_B;
        uint32_t stn = sb + (uint32_t)((i + 1) & 1) * STAGE_B;
        bool more = (i + 1) < nchunks;

        // Issue next chunk's B cp.async + A global loads (overlap with MMAs)
        if (more) {
            int k0n = (i + 1) << 5;
            CPASYNC16(stn + OFF_B + soffb, bhix + k0n);
            CPASYNC16(stn + OFF_B + soffb + 16, bhix + k0n + 8);
            CPASYNC_COMMIT();
            if (arow_ok) {
                va[0] = *(const float4*)(apix + k0n);
                va[1] = *(const float4*)(apix + k0n + 4);
                va[2] = *(const float4*)(apix + k0n + 8);
                va[3] = *(const float4*)(apix + k0n + 12);
            }
        }

        // Compute chunk i: two k16 steps
#pragma unroll
        for (int s = 0; s < 2; s++) {
            uint32_t ks = (uint32_t)s * 32;
            uint32_t a0[2][4];
            LDSM_X4(a0[0][0], a0[0][1], a0[0][2], a0[0][3], st + OFF_A + aoff0 + ks);
            LDSM_X4(a0[1][0], a0[1][1], a0[1][2], a0[1][3], st + OFF_A + aoff1 + ks);
#pragma unroll
            for (int np = 0; np < 4; np++) {
                uint32_t bh[4];
                LDSM_X4(bh[0], bh[1], bh[2], bh[3], st + OFF_B + boff[np] + ks);
#pragma unroll
                for (int mt = 0; mt < 2; mt++) {
                    MMA16816(d[mt][np * 2], a0[mt], bh[0], bh[1]);
                    MMA16816(d[mt][np * 2 + 1], a0[mt], bh[2], bh[3]);
                }
            }
        }

        // Stage next A tile, drain B cp.async, publish buffer
        if (more) {
            float fa[16] = {va[0].x, va[0].y, va[0].z, va[0].w,
                            va[1].x, va[1].y, va[1].z, va[1].w,
                            va[2].x, va[2].y, va[2].z, va[2].w,
                            va[3].x, va[3].y, va[3].z, va[3].w};
            uint32_t hv[8];
            cvt8h(fa, hv);
            cvt8h(fa + 8, hv + 4);
            STS128(stn + OFF_A + soffa, hv[0], hv[1], hv[2], hv[3]);
            STS128(stn + OFF_A + soffa + 16, hv[4], hv[5], hv[6], hv[7]);
            CPASYNC_WAIT0();
            __syncthreads();
        }
    }

    // Epilogue: wait for mapping tables, then scatter rows through g_dest.
    wait_scan_done(t, nscan);
#pragma unroll
    for (int mt = 0; mt < 2; mt++) {
        int m = bm + warp_m * 32 + mt * 16 + (lane >> 2);
        int dr0 = (m < M) ? g_dest[m] : -1;
        int dr1 = (m + 8 < M) ? g_dest[m + 8] : -1;
        int colb = bn + warp_n * 64 + (lane & 3) * 2;
#pragma unroll
        for (int nt = 0; nt < 8; nt++) {
            int col = colb + nt * 8;
            if (dr0 >= 0)
                *(float2*)(out + (size_t)dr0 * CDIM + col) =
                    make_float2(d[mt][nt][0], d[mt][nt][1]);
            if (dr1 >= 0)
                *(float2*)(out + (size_t)dr1 * CDIM + col) =
                    make_float2(d[mt][nt][2], d[mt][nt][3]);
        }
    }
}

extern "C" void kernel_launch(void* const* d_in, const int* in_sizes, int n_in,
                              void* d_out, int out_size) {
    const float* x = (const float*)d_in[0];
    const float* w = (const float*)d_in[1];
    const int* ch = (const int*)d_in[2];
    float* out = (float*)d_out;

    const int C = CDIM;
    long n_rows = (long)in_sizes[0] / C;
    int T = in_sizes[2];                       // leaf_num + nonleaf count
    int out_rows = out_size / C;
    int prefix = out_rows - T;
    long rem = n_rows - prefix;                // = L + numd,  numd = 8*(T - L)
    int L = (int)((8L * T - rem) / 7);
    int Dn = T - L;                            // nonleaf count = GEMM M
    long numd = 8L * Dn;
    int K = 8 * C;                             // 2048

    const float* A = x + (size_t)(n_rows - numd) * C;

    int nb = (T + 1023) / 1024;                // 98 (must be <= 256)
    int nbsplit = (CDIM * KDIM) / 1024;        // 512 blocks
    scan1_bsplit_kernel<<<nb + nbsplit, 256>>>(w, ch, T, nb);

    int ngemm = ((Dn + BM - 1) / BM) * 2;      // 782
    int ncopy = (out_rows * 8 + 255) / 256;    // 938
    cudaFuncSetAttribute(fused_kernel, cudaFuncAttributeMaxDynamicSharedMemorySize,
                         GEMM_SMEM);
    fused_kernel<<<nb + ngemm + ncopy, 256, GEMM_SMEM>>>(A, x, ch, out, Dn, K,
                                                         nb, ngemm, prefix,
                                                         out_rows, T);
}